// round 1
// baseline (speedup 1.0000x reference)
#include <cuda_runtime.h>
#include <cstdint>

#define NPTS   300000
#define KOFF   27
#define NPAIR  100000
#define CIN    32
#define COUT   64
#define TOT_PAIRS (KOFF * NPAIR)
#define EPS    1e-5
#define NEG_SLOPE 0.01f

// ---------------- device scratch (no allocations allowed) ----------------
__device__ int    g_is64;
__device__ int    g_in32[TOT_PAIRS];
__device__ int    g_out32[TOT_PAIRS];
__device__ double g_stats[16];   // [0..7]=sum per group, [8..15]=sumsq per group

// ---------------- dtype detection + stats zero ----------------
// The reference declares int64 indices, but JAX without x64 silently produces
// int32. Detect at runtime: reading int32 data as int64 combines two indices
// (lo + hi*2^32); hi is ~uniform in [0,NPTS) so virtually every sample blows
// past NPTS. Only sample the first TOT_PAIRS/2 int64 slots (in-bounds for
// both interpretations).
__global__ void detect_kernel(const void* in_idx) {
    int t = threadIdx.x;
    if (t == 0) g_is64 = 1;
    if (t < 16) g_stats[t] = 0.0;
    __syncthreads();
    const long long* p = (const long long*)in_idx;
    long long slots = TOT_PAIRS / 2;
    long long s = (slots * t) / 256;
    long long v = p[s];
    if (v < 0 || v >= NPTS) atomicAnd(&g_is64, 0);
}

__global__ void convert_kernel(const void* in_idx, const void* out_idx) {
    int is64 = g_is64;
    int stride = gridDim.x * blockDim.x;
    for (int i = blockIdx.x * blockDim.x + threadIdx.x; i < TOT_PAIRS; i += stride) {
        int a, b;
        if (is64) {
            a = (int)((const long long*)in_idx)[i];
            b = (int)((const long long*)out_idx)[i];
        } else {
            a = ((const int*)in_idx)[i];
            b = ((const int*)out_idx)[i];
        }
        g_in32[i]  = a;
        g_out32[i] = b;
    }
}

// ---------------- conv: gather -> per-offset matmul -> scatter-add ----------------
// One warp per pair. Lane holds weight columns (2*lane, 2*lane+1) for its
// offset k in registers (loaded once per block). feats row = one 128B line,
// loaded warp-broadcast as 8x float4. Scatter via red.global.add.v2.f32:
// one warp instruction covers the full 256B output row.
__global__ __launch_bounds__(128) void conv_kernel(
    const float* __restrict__ feats,
    const float* __restrict__ weight,
    float* __restrict__ out)
{
    int k    = blockIdx.y;
    int lane = threadIdx.x & 31;
    int warp = threadIdx.x >> 5;

    const float* W = weight + k * (CIN * COUT);
    float w0[CIN], w1[CIN];
#pragma unroll
    for (int i = 0; i < CIN; i++) {
        float2 wv = *(const float2*)(W + i * COUT + 2 * lane);
        w0[i] = wv.x; w1[i] = wv.y;
    }

    const int* ii = g_in32  + k * NPAIR;
    const int* oi = g_out32 + k * NPAIR;
    int wstride = gridDim.x * 4;

    for (int p = blockIdx.x * 4 + warp; p < NPAIR; p += wstride) {
        int pi = __ldg(ii + p);
        int po = __ldg(oi + p);

        const float4* xr = (const float4*)(feats + (long long)pi * CIN);
        float x[CIN];
#pragma unroll
        for (int j = 0; j < 8; j++) ((float4*)x)[j] = __ldg(xr + j);

        float y0 = 0.f, y1 = 0.f, y2 = 0.f, y3 = 0.f;
#pragma unroll
        for (int i = 0; i < CIN; i += 2) {
            y0 = fmaf(x[i],     w0[i],     y0);
            y1 = fmaf(x[i],     w1[i],     y1);
            y2 = fmaf(x[i + 1], w0[i + 1], y2);
            y3 = fmaf(x[i + 1], w1[i + 1], y3);
        }
        float r0 = y0 + y2;
        float r1 = y1 + y3;

        float* dst = out + (long long)po * COUT + 2 * lane;
        asm volatile("red.global.add.v2.f32 [%0], {%1, %2};"
                     :: "l"(dst), "f"(r0), "f"(r1) : "memory");
    }
}

// ---------------- group stats ----------------
// blockDim = 256 (multiple of 16) so (flat_float4_index & 15) == (tid & 15):
// every thread touches exactly ONE group -> scalar accumulators, no spills.
__global__ __launch_bounds__(256) void reduce_kernel(const float* __restrict__ out) {
    __shared__ double ssum[16];
    int t = threadIdx.x;
    if (t < 16) ssum[t] = 0.0;
    __syncthreads();

    long long total4 = (long long)NPTS * COUT / 4;
    long long stride = (long long)gridDim.x * 256;
    float s = 0.f, q = 0.f;
    for (long long j = (long long)blockIdx.x * 256 + t; j < total4; j += stride) {
        float4 v = __ldg(((const float4*)out) + j);
        s += (v.x + v.y) + (v.z + v.w);
        q += (v.x * v.x + v.y * v.y) + (v.z * v.z + v.w * v.w);
    }
    // lane group = ((lane & 15) >> 1); combine lane^16 then lane^1
    s += __shfl_xor_sync(0xffffffffu, s, 16);
    q += __shfl_xor_sync(0xffffffffu, q, 16);
    s += __shfl_xor_sync(0xffffffffu, s, 1);
    q += __shfl_xor_sync(0xffffffffu, q, 1);
    int lane = t & 31;
    if ((lane & 16) == 0 && (lane & 1) == 0) {
        int g = lane >> 1;
        atomicAdd(&ssum[g],     (double)s);
        atomicAdd(&ssum[8 + g], (double)q);
    }
    __syncthreads();
    if (t < 16) atomicAdd(&g_stats[t], ssum[t]);
}

// ---------------- normalize + affine + LeakyReLU ----------------
__global__ __launch_bounds__(256) void norm_kernel(
    float* __restrict__ out,
    const float* __restrict__ gamma,
    const float* __restrict__ beta)
{
    int t  = threadIdx.x;
    int c4 = t & 15;          // float4 slot within the 64-channel row (constant per thread)
    int g  = c4 >> 1;

    double cnt = (double)NPTS * 8.0;
    double m   = g_stats[g] / cnt;
    double var = g_stats[8 + g] / cnt - m * m;
    float mean = (float)m;
    float rstd = (float)(1.0 / sqrt(var + EPS));

    float4 ga = __ldg(((const float4*)gamma) + c4);
    float4 be = __ldg(((const float4*)beta) + c4);
    float4 sc, of;
    sc.x = rstd * ga.x; of.x = be.x - mean * sc.x;
    sc.y = rstd * ga.y; of.y = be.y - mean * sc.y;
    sc.z = rstd * ga.z; of.z = be.z - mean * sc.z;
    sc.w = rstd * ga.w; of.w = be.w - mean * sc.w;

    long long total4 = (long long)NPTS * COUT / 4;
    long long stride = (long long)gridDim.x * 256;
    for (long long j = (long long)blockIdx.x * 256 + t; j < total4; j += stride) {
        float4 v = ((float4*)out)[j];
        v.x = fmaf(v.x, sc.x, of.x);
        v.y = fmaf(v.y, sc.y, of.y);
        v.z = fmaf(v.z, sc.z, of.z);
        v.w = fmaf(v.w, sc.w, of.w);
        v.x = v.x >= 0.f ? v.x : NEG_SLOPE * v.x;
        v.y = v.y >= 0.f ? v.y : NEG_SLOPE * v.y;
        v.z = v.z >= 0.f ? v.z : NEG_SLOPE * v.z;
        v.w = v.w >= 0.f ? v.w : NEG_SLOPE * v.w;
        ((float4*)out)[j] = v;
    }
}

// ---------------- launcher ----------------
extern "C" void kernel_launch(void* const* d_in, const int* in_sizes, int n_in,
                              void* d_out, int out_size) {
    const float* feats  = (const float*)d_in[0];
    const float* weight = (const float*)d_in[1];
    const float* gamma  = (const float*)d_in[2];
    const float* beta   = (const float*)d_in[3];
    const void*  in_idx = d_in[4];
    const void*  out_idx= d_in[5];
    float* out = (float*)d_out;

    cudaMemsetAsync(d_out, 0, (size_t)out_size * sizeof(float), 0);
    detect_kernel<<<1, 256>>>(in_idx);
    convert_kernel<<<1320, 256>>>(in_idx, out_idx);
    conv_kernel<<<dim3(100, KOFF), 128>>>(feats, weight, out);
    reduce_kernel<<<296, 256>>>(out);
    norm_kernel<<<592, 256>>>(out, gamma, beta);
}